// round 1
// baseline (speedup 1.0000x reference)
#include <cuda_runtime.h>
#include <math.h>

// Problem constants:
// x: [8, 64, 768]      -> 393216 floats
// y: [8, 4096, 768]    -> 25165824 floats
// W_qkv: [2304, 768]   -> 1769472 floats
// W_proj: [768, 768]   -> 589824 floats
// b_proj: [768]
// out: [8, 4096, 768]  -> 25165824 floats
// H = 12, hd = 64, scale = 1/8

// ---------------- scratch (device globals; allocation-free) ----------------
__device__ float g_q[512 * 768];                 // x @ Wq^T               (1.5 MB)
__device__ float g_kv[32768L * 1536];            // y @ Wkv^T  [k | v]     (192 MB)
__device__ float g_attn[6144L * 4096];           // logits/softmax [B*768, 4096] (96 MB)
__device__ float g_opre[32768L * 768];           // attn_t * v, merged [B*N2, C] (96 MB)

// ---------------- generic tiled SGEMM: C[M,N] = A[M,K] @ B[N,K]^T (+bias) ----------------
// All dims are multiples of tiles for every call site (checked below).
template <int BM, int BN, int BK, int TM, int TN, bool BIAS>
__global__ void __launch_bounds__(256) sgemm_abt(
    const float* __restrict__ A, const float* __restrict__ Bw,
    float* __restrict__ Cmat, const float* __restrict__ bias,
    int M, int N, int K)
{
    __shared__ float As[BK][BM];
    __shared__ float Bs[BK][BN];
    constexpr int THREADS = (BM / TM) * (BN / TN);
    static_assert(THREADS == 256, "grid math assumes 256 threads");
    const int tid  = threadIdx.x;
    constexpr int K4 = BK / 4;
    const int lrow = tid / K4;            // row within tile being loaded
    const int lcol = (tid % K4) * 4;      // k-offset (float4)
    constexpr int ROWS_PER = THREADS / K4;

    const int trow = (tid / (BN / TN)) * TM;
    const int tcol = (tid % (BN / TN)) * TN;

    const float* Ab  = A  + (size_t)blockIdx.y * BM * K;
    const float* Bbp = Bw + (size_t)blockIdx.x * BN * K;

    float acc[TM][TN] = {};

    for (int k0 = 0; k0 < K; k0 += BK) {
        #pragma unroll
        for (int r = 0; r < BM; r += ROWS_PER) {
            float4 v = *(const float4*)(Ab + (size_t)(r + lrow) * K + k0 + lcol);
            As[lcol + 0][r + lrow] = v.x;
            As[lcol + 1][r + lrow] = v.y;
            As[lcol + 2][r + lrow] = v.z;
            As[lcol + 3][r + lrow] = v.w;
        }
        #pragma unroll
        for (int r = 0; r < BN; r += ROWS_PER) {
            float4 v = *(const float4*)(Bbp + (size_t)(r + lrow) * K + k0 + lcol);
            Bs[lcol + 0][r + lrow] = v.x;
            Bs[lcol + 1][r + lrow] = v.y;
            Bs[lcol + 2][r + lrow] = v.z;
            Bs[lcol + 3][r + lrow] = v.w;
        }
        __syncthreads();
        #pragma unroll
        for (int kk = 0; kk < BK; kk++) {
            float regM[TM], regN[TN];
            #pragma unroll
            for (int i = 0; i < TM; i += 4)
                *(float4*)&regM[i] = *(const float4*)&As[kk][trow + i];
            #pragma unroll
            for (int j = 0; j < TN; j += 4)
                *(float4*)&regN[j] = *(const float4*)&Bs[kk][tcol + j];
            #pragma unroll
            for (int i = 0; i < TM; i++)
                #pragma unroll
                for (int j = 0; j < TN; j++)
                    acc[i][j] = fmaf(regM[i], regN[j], acc[i][j]);
        }
        __syncthreads();
    }

    float* Cb = Cmat + (size_t)blockIdx.y * BM * N + (size_t)blockIdx.x * BN;
    #pragma unroll
    for (int i = 0; i < TM; i++) {
        #pragma unroll
        for (int j = 0; j < TN; j += 4) {
            float4 v = { acc[i][j], acc[i][j + 1], acc[i][j + 2], acc[i][j + 3] };
            if (BIAS) {
                const float4 bv = *(const float4*)&bias[blockIdx.x * BN + tcol + j];
                v.x += bv.x; v.y += bv.y; v.z += bv.z; v.w += bv.w;
            }
            *(float4*)(Cb + (size_t)(trow + i) * N + tcol + j) = v;
        }
    }
}

// ---------------- attention logits: attn[b*768+h*64+i][j] = scale * q_bh[i,:]·k_bh[j,:] ----------------
// grid: (N2/128, B*H), 256 threads. Each block: 64 (i) x 128 (j) tile, K=64 fully in smem.
__global__ void __launch_bounds__(256) attn_logits(
    const float* __restrict__ q, const float* __restrict__ kv,
    float* __restrict__ attn)
{
    const int bh = blockIdx.y;
    const int b = bh / 12, h = bh % 12;
    const int j0 = blockIdx.x * 128;
    __shared__ float Qs[64][65];
    __shared__ float Ks[128][65];
    const int tid = threadIdx.x;

    // load Q head tile [64 x 64] (natural layout, float4 from gmem, scalar smem stores)
    for (int t = tid; t < 64 * 16; t += 256) {
        const int i = t >> 4; const int d4 = (t & 15) << 2;
        float4 v = *(const float4*)&q[(size_t)(b * 64 + i) * 768 + h * 64 + d4];
        Qs[i][d4] = v.x; Qs[i][d4 + 1] = v.y; Qs[i][d4 + 2] = v.z; Qs[i][d4 + 3] = v.w;
    }
    // load K head tile [128 x 64] (k part = cols [0,768) of g_kv)
    for (int t = tid; t < 128 * 16; t += 256) {
        const int j = t >> 4; const int d4 = (t & 15) << 2;
        float4 v = *(const float4*)&kv[(size_t)(b * 4096 + j0 + j) * 1536 + h * 64 + d4];
        Ks[j][d4] = v.x; Ks[j][d4 + 1] = v.y; Ks[j][d4 + 2] = v.z; Ks[j][d4 + 3] = v.w;
    }
    __syncthreads();

    const int trow = (tid >> 4) * 4;   // i base: 0..60
    const int tcol = tid & 15;         // j cols: tcol + 16*jj (strided -> conflict-free LDS)
    float acc[4][8] = {};
    #pragma unroll 4
    for (int d = 0; d < 64; d++) {
        float qr[4], kr[8];
        #pragma unroll
        for (int i = 0; i < 4; i++) qr[i] = Qs[trow + i][d];
        #pragma unroll
        for (int j = 0; j < 8; j++) kr[j] = Ks[tcol + 16 * j][d];
        #pragma unroll
        for (int i = 0; i < 4; i++)
            #pragma unroll
            for (int j = 0; j < 8; j++)
                acc[i][j] = fmaf(qr[i], kr[j], acc[i][j]);
    }
    const float scale = 0.125f;  // 64^-0.5
    #pragma unroll
    for (int i = 0; i < 4; i++) {
        float* row = attn + (size_t)(b * 768 + h * 64 + trow + i) * 4096 + j0;
        #pragma unroll
        for (int j = 0; j < 8; j++)
            row[tcol + 16 * j] = acc[i][j] * scale;
    }
}

// ---------------- row softmax over 4096, one block per row ----------------
__global__ void __launch_bounds__(256) softmax4096(float* __restrict__ a)
{
    float* p = a + (size_t)blockIdx.x * 4096;
    const int tid = threadIdx.x;
    float4 v[4];
    #pragma unroll
    for (int t = 0; t < 4; t++) v[t] = *(const float4*)&p[tid * 4 + t * 1024];

    float m = -1e30f;
    #pragma unroll
    for (int t = 0; t < 4; t++)
        m = fmaxf(m, fmaxf(fmaxf(v[t].x, v[t].y), fmaxf(v[t].z, v[t].w)));

    __shared__ float sh[8];
    #pragma unroll
    for (int o = 16; o; o >>= 1) m = fmaxf(m, __shfl_xor_sync(0xffffffffu, m, o));
    if ((tid & 31) == 0) sh[tid >> 5] = m;
    __syncthreads();
    m = fmaxf(fmaxf(fmaxf(sh[0], sh[1]), fmaxf(sh[2], sh[3])),
              fmaxf(fmaxf(sh[4], sh[5]), fmaxf(sh[6], sh[7])));

    float s = 0.f;
    #pragma unroll
    for (int t = 0; t < 4; t++) {
        v[t].x = __expf(v[t].x - m); v[t].y = __expf(v[t].y - m);
        v[t].z = __expf(v[t].z - m); v[t].w = __expf(v[t].w - m);
        s += v[t].x + v[t].y + v[t].z + v[t].w;
    }
    __syncthreads();   // protect sh before reuse
    #pragma unroll
    for (int o = 16; o; o >>= 1) s += __shfl_xor_sync(0xffffffffu, s, o);
    if ((tid & 31) == 0) sh[tid >> 5] = s;
    __syncthreads();
    s = sh[0] + sh[1] + sh[2] + sh[3] + sh[4] + sh[5] + sh[6] + sh[7];
    const float inv = 1.0f / s;
    #pragma unroll
    for (int t = 0; t < 4; t++) {
        v[t].x *= inv; v[t].y *= inv; v[t].z *= inv; v[t].w *= inv;
        *(float4*)&p[tid * 4 + t * 1024] = v[t];
    }
}

// ---------------- o_pre[b*4096+n][c] = attn[b*768+c][n] * v[b*4096+n][768+c] ----------------
// 32x32 smem transpose fused with elementwise multiply. grid (N2/32, C/32, B), block 32x8.
__global__ void __launch_bounds__(256) trans_mul(
    const float* __restrict__ attn, const float* __restrict__ kv,
    float* __restrict__ opre)
{
    __shared__ float tile[32][33];
    const int b  = blockIdx.z;
    const int n0 = blockIdx.x * 32;
    const int c0 = blockIdx.y * 32;
    const int tx = threadIdx.x, ty = threadIdx.y;
    #pragma unroll
    for (int r = ty; r < 32; r += 8)
        tile[r][tx] = attn[(size_t)(b * 768 + c0 + r) * 4096 + n0 + tx];
    __syncthreads();
    #pragma unroll
    for (int r = ty; r < 32; r += 8) {
        const int n = n0 + r, c = c0 + tx;
        const float vv = kv[(size_t)(b * 4096 + n) * 1536 + 768 + c];
        opre[(size_t)(b * 4096 + n) * 768 + c] = tile[tx][r] * vv;
    }
}

// ---------------- launch ----------------
extern "C" void kernel_launch(void* const* d_in, const int* in_sizes, int n_in,
                              void* d_out, int out_size)
{
    // Identify inputs by element count (all distinct) — robust to ordering.
    const float *x = nullptr, *y = nullptr, *Wqkv = nullptr, *Wproj = nullptr, *bproj = nullptr;
    for (int i = 0; i < n_in; i++) {
        switch (in_sizes[i]) {
            case 393216:   x     = (const float*)d_in[i]; break;
            case 25165824: y     = (const float*)d_in[i]; break;
            case 1769472:  Wqkv  = (const float*)d_in[i]; break;
            case 589824:   Wproj = (const float*)d_in[i]; break;
            case 768:      bproj = (const float*)d_in[i]; break;
        }
    }
    float* out = (float*)d_out;

    float *qbuf, *kvbuf, *attnbuf, *oprebuf;
    cudaGetSymbolAddress((void**)&qbuf,    g_q);
    cudaGetSymbolAddress((void**)&kvbuf,   g_kv);
    cudaGetSymbolAddress((void**)&attnbuf, g_attn);
    cudaGetSymbolAddress((void**)&oprebuf, g_opre);

    // 1) q = x @ Wq^T : [512,768] x [768,768]
    sgemm_abt<64, 64, 16, 4, 4, false><<<dim3(768 / 64, 512 / 64), 256>>>(
        x, Wqkv, qbuf, nullptr, 512, 768, 768);

    // 2) kv = y @ Wkv^T : [32768,768] x [1536,768]  (Wkv = rows 768..2303 of W_qkv)
    sgemm_abt<128, 128, 16, 8, 8, false><<<dim3(1536 / 128, 32768 / 128), 256>>>(
        y, Wqkv + 768 * 768, kvbuf, nullptr, 32768, 1536, 768);

    // 3) logits (scaled)
    attn_logits<<<dim3(4096 / 128, 8 * 12), 256>>>(qbuf, kvbuf, attnbuf);

    // 4) softmax over last axis (6144 rows of 4096)
    softmax4096<<<6144, 256>>>(attnbuf);

    // 5) attn_t * v, merged layout [B*N2, C]
    trans_mul<<<dim3(4096 / 32, 768 / 32, 8), dim3(32, 8)>>>(attnbuf, kvbuf, oprebuf);

    // 6) out = o_pre @ W_proj^T + b_proj : [32768,768] x [768,768]
    sgemm_abt<128, 128, 16, 8, 8, true><<<dim3(768 / 128, 32768 / 128), 256>>>(
        oprebuf, Wproj, out, bproj, 32768, 768, 768);
}

// round 3
// speedup vs baseline: 2.1618x; 2.1618x over previous
#include <cuda_runtime.h>
#include <cuda_fp16.h>
#include <cstdint>
#include <math.h>

// ============================================================================
// CrossAttention on GB300 via compute_103-legal tensor cores (mma.sync fp16).
// x: [8,64,768], y: [8,4096,768], W_qkv: [2304,768], W_proj: [768,768],
// b_proj: [768], out: [8,4096,768]. H=12, hd=64, scale=1/8.
//
// Precision: fp32 emulated as 3-term fp16 split (A_hi*B_hi + A_lo*B_hi +
// A_hi*B_lo), fp32 accumulators -> rel err ~1e-6.
// ============================================================================

// ---------------- scratch (device globals; allocation-free) ----------------
__device__ float  g_q[512 * 768];              // x @ Wq^T (fp32)
__device__ __half g_yh[25165824];              // y hi fp16
__device__ __half g_yl[25165824];              // y lo fp16
__device__ __half g_wkvh[1536 * 768];
__device__ __half g_wkvl[1536 * 768];
__device__ __half g_wph[768 * 768];
__device__ __half g_wpl[768 * 768];
__device__ float  g_kv[32768L * 1536];         // y @ Wkv^T (fp32) [k | v]
__device__ float  g_attn[6144L * 4096];        // logits/softmax
__device__ __half g_oh[32768L * 768];          // (attn_t * v) hi
__device__ __half g_ol[32768L * 768];          // (attn_t * v) lo

// ============================================================================
// low-level helpers (all sm_80-level PTX; legal at compute_103)
// ============================================================================
__device__ __forceinline__ uint32_t smem_u32(const void* p) {
    uint32_t a;
    asm("{ .reg .u64 t; cvta.to.shared.u64 t, %1; cvt.u32.u64 %0, t; }" : "=r"(a) : "l"(p));
    return a;
}
__device__ __forceinline__ void cp_async16(uint32_t s, const void* g) {
    asm volatile("cp.async.cg.shared.global [%0], [%1], 16;\n" :: "r"(s), "l"(g));
}
__device__ __forceinline__ void cp_commit() {
    asm volatile("cp.async.commit_group;\n");
}
template <int N>
__device__ __forceinline__ void cp_wait() {
    asm volatile("cp.async.wait_group %0;\n" :: "n"(N));
}
__device__ __forceinline__ void ldsm_x4(uint32_t* r, uint32_t addr) {
    asm volatile("ldmatrix.sync.aligned.m8n8.x4.shared.b16 {%0,%1,%2,%3}, [%4];\n"
                 : "=r"(r[0]), "=r"(r[1]), "=r"(r[2]), "=r"(r[3]) : "r"(addr));
}
__device__ __forceinline__ void mma16816(float* c, const uint32_t* a, const uint32_t* b) {
    asm volatile("mma.sync.aligned.m16n8k16.row.col.f32.f16.f16.f32 "
                 "{%0,%1,%2,%3}, {%4,%5,%6,%7}, {%8,%9}, {%0,%1,%2,%3};\n"
                 : "+f"(c[0]), "+f"(c[1]), "+f"(c[2]), "+f"(c[3])
                 : "r"(a[0]), "r"(a[1]), "r"(a[2]), "r"(a[3]), "r"(b[0]), "r"(b[1]));
}

// ============================================================================
// HMMA split-fp16 GEMM: C[M,N] = A[M,K] @ B[N,K]^T (+bias)
// Block tile 128x128, BK=64 (fp16), 3-stage cp.async pipeline, 8 warps.
// 3 K-passes: (Ahi,Bhi), (Alo,Bhi), (Ahi,Blo) into the same accumulators.
// ============================================================================
static constexpr int STAGES = 3;
static constexpr int STAGE_BYTES = 32768;               // 16KB A + 16KB B
static constexpr int GEMM_SMEM = STAGES * STAGE_BYTES;  // 96 KB

template <bool BIAS>
__global__ void __launch_bounds__(256) hmma_gemm(
    const __half* __restrict__ Ahi, const __half* __restrict__ Alo,
    const __half* __restrict__ Bhi, const __half* __restrict__ Blo,
    float* __restrict__ C, const float* __restrict__ bias,
    int K, int ldC)
{
    extern __shared__ char smem[];
    const uint32_t sb = smem_u32(smem);
    const int tid  = threadIdx.x;
    const int wid  = tid >> 5;
    const int lane = tid & 31;
    const int m_warp = (wid & 1) * 64;
    const int n_warp = (wid >> 1) * 32;

    const size_t arow0 = (size_t)blockIdx.y * 128;
    const size_t brow0 = (size_t)blockIdx.x * 128;
    const int ncK = K >> 6;          // chunks per pass
    const int total = 3 * ncK;

    // per-thread load coords (A/B tiles: 128 rows x 8 x 16B chunks)
    const int lrow_base = tid >> 3;   // 0..31, +32*i
    const int lch = tid & 7;

    auto issue_chunk = [&](int t) {
        const int pass = t / ncK;
        const int kc = t - pass * ncK;
        const __half* Ap = (pass == 1) ? Alo : Ahi;
        const __half* Bp = (pass == 2) ? Blo : Bhi;
        const int k0 = kc << 6;
        const uint32_t sa = sb + (t % STAGES) * STAGE_BYTES;
        const uint32_t sbb = sa + 16384;
        #pragma unroll
        for (int i = 0; i < 4; i++) {
            const int row = lrow_base + i * 32;
            const __half* g = Ap + (arow0 + row) * (size_t)K + k0 + lch * 8;
            cp_async16(sa + row * 128 + ((lch ^ (row & 7)) << 4), g);
        }
        #pragma unroll
        for (int i = 0; i < 4; i++) {
            const int row = lrow_base + i * 32;
            const __half* g = Bp + (brow0 + row) * (size_t)K + k0 + lch * 8;
            cp_async16(sbb + row * 128 + ((lch ^ (row & 7)) << 4), g);
        }
    };

    float acc[4][4][4] = {};

    // prologue
    #pragma unroll
    for (int s = 0; s < STAGES - 1; s++) { issue_chunk(s); cp_commit(); }

    for (int t = 0; t < total; t++) {
        cp_wait<STAGES - 2>();
        __syncthreads();
        if (t + STAGES - 1 < total) issue_chunk(t + STAGES - 1);
        cp_commit();

        const uint32_t sa = sb + (t % STAGES) * STAGE_BYTES;
        const uint32_t sbb = sa + 16384;
        #pragma unroll
        for (int ks = 0; ks < 4; ks++) {
            uint32_t afr[4][4];
            #pragma unroll
            for (int mi = 0; mi < 4; mi++) {
                const int r = m_warp + mi * 16 + (lane & 15);
                const int kk = ks * 16 + (lane >> 4) * 8;
                ldsm_x4(afr[mi], sa + r * 128 + ((((kk >> 3) ^ (r & 7))) << 4));
            }
            uint32_t bfr[4][2];
            #pragma unroll
            for (int nh = 0; nh < 2; nh++) {
                const int g = lane >> 3;
                const int nr = n_warp + nh * 16 + ((g >> 1) << 3) + (lane & 7);
                const int kk = ks * 16 + ((g & 1) << 3);
                uint32_t r4[4];
                ldsm_x4(r4, sbb + nr * 128 + ((((kk >> 3) ^ (nr & 7))) << 4));
                bfr[nh * 2][0] = r4[0]; bfr[nh * 2][1] = r4[1];
                bfr[nh * 2 + 1][0] = r4[2]; bfr[nh * 2 + 1][1] = r4[3];
            }
            #pragma unroll
            for (int mi = 0; mi < 4; mi++)
                #pragma unroll
                for (int ni = 0; ni < 4; ni++)
                    mma16816(acc[mi][ni], afr[mi], bfr[ni]);
        }
    }

    // epilogue: fragment layout m16n8: c0,c1 -> (row lane/4, col 2*(lane%4)); c2,c3 -> row+8
    const int mg0 = (int)arow0 + m_warp + (lane >> 2);
    const int ng0 = (int)brow0 + n_warp + (lane & 3) * 2;
    #pragma unroll
    for (int mi = 0; mi < 4; mi++) {
        #pragma unroll
        for (int ni = 0; ni < 4; ni++) {
            const int m = mg0 + mi * 16;
            const int n = ng0 + ni * 8;
            float2 v0 = { acc[mi][ni][0], acc[mi][ni][1] };
            float2 v1 = { acc[mi][ni][2], acc[mi][ni][3] };
            if (BIAS) {
                const float2 bv = *(const float2*)&bias[n];
                v0.x += bv.x; v0.y += bv.y; v1.x += bv.x; v1.y += bv.y;
            }
            *(float2*)&C[(size_t)m * ldC + n] = v0;
            *(float2*)&C[(size_t)(m + 8) * ldC + n] = v1;
        }
    }
}

// ============================================================================
// fp32 -> (hi, lo) fp16 split conversion
// ============================================================================
__device__ __forceinline__ void split_h(float x, __half& h, __half& l) {
    h = __float2half_rn(x);
    l = __float2half_rn(x - __half2float(h));
}

__global__ void __launch_bounds__(256) conv_split4(const float* __restrict__ in,
                                                   __half* __restrict__ hi,
                                                   __half* __restrict__ lo, int n4)
{
    const int i = blockIdx.x * blockDim.x + threadIdx.x;
    if (i >= n4) return;
    const float4 v = *(const float4*)&in[i * 4];
    __half h[4], l[4];
    split_h(v.x, h[0], l[0]); split_h(v.y, h[1], l[1]);
    split_h(v.z, h[2], l[2]); split_h(v.w, h[3], l[3]);
    *(uint2*)&hi[i * 4] = *(uint2*)h;
    *(uint2*)&lo[i * 4] = *(uint2*)l;
}

// ============================================================================
// fp32 tiled SGEMM for tiny q projection: C = A @ B^T
// ============================================================================
template <int BM, int BN, int BK, int TM, int TN>
__global__ void __launch_bounds__(256) sgemm_abt(
    const float* __restrict__ A, const float* __restrict__ Bw,
    float* __restrict__ Cmat, int M, int N, int K)
{
    __shared__ float As[BK][BM];
    __shared__ float Bs[BK][BN];
    const int tid = threadIdx.x;
    constexpr int K4 = BK / 4;
    const int lrow = tid / K4;
    const int lcol = (tid % K4) * 4;
    constexpr int ROWS_PER = 256 / K4;
    const int trow = (tid / (BN / TN)) * TM;
    const int tcol = (tid % (BN / TN)) * TN;
    const float* Ab = A + (size_t)blockIdx.y * BM * K;
    const float* Bb = Bw + (size_t)blockIdx.x * BN * K;
    float acc[TM][TN] = {};
    for (int k0 = 0; k0 < K; k0 += BK) {
        #pragma unroll
        for (int r = 0; r < BM; r += ROWS_PER) {
            float4 v = *(const float4*)(Ab + (size_t)(r + lrow) * K + k0 + lcol);
            As[lcol][r + lrow] = v.x; As[lcol + 1][r + lrow] = v.y;
            As[lcol + 2][r + lrow] = v.z; As[lcol + 3][r + lrow] = v.w;
        }
        #pragma unroll
        for (int r = 0; r < BN; r += ROWS_PER) {
            float4 v = *(const float4*)(Bb + (size_t)(r + lrow) * K + k0 + lcol);
            Bs[lcol][r + lrow] = v.x; Bs[lcol + 1][r + lrow] = v.y;
            Bs[lcol + 2][r + lrow] = v.z; Bs[lcol + 3][r + lrow] = v.w;
        }
        __syncthreads();
        #pragma unroll
        for (int kk = 0; kk < BK; kk++) {
            float rm[TM], rn[TN];
            #pragma unroll
            for (int i = 0; i < TM; i += 4) *(float4*)&rm[i] = *(const float4*)&As[kk][trow + i];
            #pragma unroll
            for (int j = 0; j < TN; j += 4) *(float4*)&rn[j] = *(const float4*)&Bs[kk][tcol + j];
            #pragma unroll
            for (int i = 0; i < TM; i++)
                #pragma unroll
                for (int j = 0; j < TN; j++) acc[i][j] = fmaf(rm[i], rn[j], acc[i][j]);
        }
        __syncthreads();
    }
    float* Cb = Cmat + (size_t)blockIdx.y * BM * N + (size_t)blockIdx.x * BN;
    #pragma unroll
    for (int i = 0; i < TM; i++)
        #pragma unroll
        for (int j = 0; j < TN; j += 4) {
            float4 v = { acc[i][j], acc[i][j + 1], acc[i][j + 2], acc[i][j + 3] };
            *(float4*)(Cb + (size_t)(trow + i) * N + tcol + j) = v;
        }
}

// ============================================================================
// attention logits (fp32): attn[b*768+h*64+i][j] = scale * q_bh[i,:]·k_bh[j,:]
// ============================================================================
__global__ void __launch_bounds__(256) attn_logits(
    const float* __restrict__ q, const float* __restrict__ kv, float* __restrict__ attn)
{
    const int bh = blockIdx.y;
    const int b = bh / 12, h = bh % 12;
    const int j0 = blockIdx.x * 128;
    __shared__ float Qs[64][65];
    __shared__ float Ks[128][65];
    const int tid = threadIdx.x;
    for (int t = tid; t < 64 * 16; t += 256) {
        const int i = t >> 4; const int d4 = (t & 15) << 2;
        float4 v = *(const float4*)&q[(size_t)(b * 64 + i) * 768 + h * 64 + d4];
        Qs[i][d4] = v.x; Qs[i][d4 + 1] = v.y; Qs[i][d4 + 2] = v.z; Qs[i][d4 + 3] = v.w;
    }
    for (int t = tid; t < 128 * 16; t += 256) {
        const int j = t >> 4; const int d4 = (t & 15) << 2;
        float4 v = *(const float4*)&kv[(size_t)(b * 4096 + j0 + j) * 1536 + h * 64 + d4];
        Ks[j][d4] = v.x; Ks[j][d4 + 1] = v.y; Ks[j][d4 + 2] = v.z; Ks[j][d4 + 3] = v.w;
    }
    __syncthreads();
    const int trow = (tid >> 4) * 4;
    const int tcol = tid & 15;
    float acc[4][8] = {};
    #pragma unroll 4
    for (int d = 0; d < 64; d++) {
        float qr[4], kr[8];
        #pragma unroll
        for (int i = 0; i < 4; i++) qr[i] = Qs[trow + i][d];
        #pragma unroll
        for (int j = 0; j < 8; j++) kr[j] = Ks[tcol + 16 * j][d];
        #pragma unroll
        for (int i = 0; i < 4; i++)
            #pragma unroll
            for (int j = 0; j < 8; j++) acc[i][j] = fmaf(qr[i], kr[j], acc[i][j]);
    }
    #pragma unroll
    for (int i = 0; i < 4; i++) {
        float* row = attn + (size_t)(b * 768 + h * 64 + trow + i) * 4096 + j0;
        #pragma unroll
        for (int j = 0; j < 8; j++) row[tcol + 16 * j] = acc[i][j] * 0.125f;
    }
}

// ============================================================================
// row softmax over 4096
// ============================================================================
__global__ void __launch_bounds__(256) softmax4096(float* __restrict__ a)
{
    float* p = a + (size_t)blockIdx.x * 4096;
    const int tid = threadIdx.x;
    float4 v[4];
    #pragma unroll
    for (int t = 0; t < 4; t++) v[t] = *(const float4*)&p[tid * 4 + t * 1024];
    float m = -1e30f;
    #pragma unroll
    for (int t = 0; t < 4; t++)
        m = fmaxf(m, fmaxf(fmaxf(v[t].x, v[t].y), fmaxf(v[t].z, v[t].w)));
    __shared__ float sh[8];
    #pragma unroll
    for (int o = 16; o; o >>= 1) m = fmaxf(m, __shfl_xor_sync(0xffffffffu, m, o));
    if ((tid & 31) == 0) sh[tid >> 5] = m;
    __syncthreads();
    m = fmaxf(fmaxf(fmaxf(sh[0], sh[1]), fmaxf(sh[2], sh[3])),
              fmaxf(fmaxf(sh[4], sh[5]), fmaxf(sh[6], sh[7])));
    float s = 0.f;
    #pragma unroll
    for (int t = 0; t < 4; t++) {
        v[t].x = __expf(v[t].x - m); v[t].y = __expf(v[t].y - m);
        v[t].z = __expf(v[t].z - m); v[t].w = __expf(v[t].w - m);
        s += v[t].x + v[t].y + v[t].z + v[t].w;
    }
    __syncthreads();
    #pragma unroll
    for (int o = 16; o; o >>= 1) s += __shfl_xor_sync(0xffffffffu, s, o);
    if ((tid & 31) == 0) sh[tid >> 5] = s;
    __syncthreads();
    s = sh[0] + sh[1] + sh[2] + sh[3] + sh[4] + sh[5] + sh[6] + sh[7];
    const float inv = 1.0f / s;
    #pragma unroll
    for (int t = 0; t < 4; t++) {
        v[t].x *= inv; v[t].y *= inv; v[t].z *= inv; v[t].w *= inv;
        *(float4*)&p[tid * 4 + t * 1024] = v[t];
    }
}

// ============================================================================
// o_pre = attn^T * v, emitted as (hi, lo) fp16 split
// ============================================================================
__global__ void __launch_bounds__(256) trans_mul_split(
    const float* __restrict__ attn, const float* __restrict__ kv,
    __half* __restrict__ ohi, __half* __restrict__ olo)
{
    __shared__ float tile[32][33];
    const int b = blockIdx.z;
    const int n0 = blockIdx.x * 32;
    const int c0 = blockIdx.y * 32;
    const int tx = threadIdx.x, ty = threadIdx.y;
    #pragma unroll
    for (int r = ty; r < 32; r += 8)
        tile[r][tx] = attn[(size_t)(b * 768 + c0 + r) * 4096 + n0 + tx];
    __syncthreads();
    #pragma unroll
    for (int r = ty; r < 32; r += 8) {
        const int n = n0 + r, c = c0 + tx;
        const float vv = kv[(size_t)(b * 4096 + n) * 1536 + 768 + c];
        const float o = tile[tx][r] * vv;
        __half h, l; split_h(o, h, l);
        const size_t idx = (size_t)(b * 4096 + n) * 768 + c;
        ohi[idx] = h; olo[idx] = l;
    }
}

// ============================================================================
// launch
// ============================================================================
extern "C" void kernel_launch(void* const* d_in, const int* in_sizes, int n_in,
                              void* d_out, int out_size)
{
    const float *x = nullptr, *y = nullptr, *Wqkv = nullptr, *Wproj = nullptr, *bproj = nullptr;
    for (int i = 0; i < n_in; i++) {
        switch (in_sizes[i]) {
            case 393216:   x     = (const float*)d_in[i]; break;
            case 25165824: y     = (const float*)d_in[i]; break;
            case 1769472:  Wqkv  = (const float*)d_in[i]; break;
            case 589824:   Wproj = (const float*)d_in[i]; break;
            case 768:      bproj = (const float*)d_in[i]; break;
        }
    }
    float* out = (float*)d_out;

    float *qbuf, *kvbuf, *attnbuf;
    __half *yh, *yl, *wkvh, *wkvl, *wph, *wpl, *oh, *ol;
    cudaGetSymbolAddress((void**)&qbuf,    g_q);
    cudaGetSymbolAddress((void**)&kvbuf,   g_kv);
    cudaGetSymbolAddress((void**)&attnbuf, g_attn);
    cudaGetSymbolAddress((void**)&yh,   g_yh);
    cudaGetSymbolAddress((void**)&yl,   g_yl);
    cudaGetSymbolAddress((void**)&wkvh, g_wkvh);
    cudaGetSymbolAddress((void**)&wkvl, g_wkvl);
    cudaGetSymbolAddress((void**)&wph,  g_wph);
    cudaGetSymbolAddress((void**)&wpl,  g_wpl);
    cudaGetSymbolAddress((void**)&oh,   g_oh);
    cudaGetSymbolAddress((void**)&ol,   g_ol);

    cudaFuncSetAttribute(hmma_gemm<false>, cudaFuncAttributeMaxDynamicSharedMemorySize, GEMM_SMEM);
    cudaFuncSetAttribute(hmma_gemm<true>,  cudaFuncAttributeMaxDynamicSharedMemorySize, GEMM_SMEM);

    // 0) fp32 -> fp16 hi/lo splits
    conv_split4<<<25165824 / 4 / 256, 256>>>(y, yh, yl, 25165824 / 4);
    conv_split4<<<1179648 / 4 / 256, 256>>>(Wqkv + 768 * 768, wkvh, wkvl, 1179648 / 4);
    conv_split4<<<589824 / 4 / 256, 256>>>(Wproj, wph, wpl, 589824 / 4);

    // 1) q = x @ Wq^T (fp32, tiny)
    sgemm_abt<64, 64, 16, 4, 4><<<dim3(768 / 64, 512 / 64), 256>>>(x, Wqkv, qbuf, 512, 768, 768);

    // 2) kv = y @ Wkv^T via HMMA split-fp16: [32768,768] x [1536,768]
    hmma_gemm<false><<<dim3(1536 / 128, 32768 / 128), 256, GEMM_SMEM>>>(
        yh, yl, wkvh, wkvl, kvbuf, nullptr, 768, 1536);

    // 3) logits
    attn_logits<<<dim3(4096 / 128, 8 * 12), 256>>>(qbuf, kvbuf, attnbuf);

    // 4) softmax
    softmax4096<<<6144, 256>>>(attnbuf);

    // 5) attn_t * v -> fp16 hi/lo
    trans_mul_split<<<dim3(4096 / 32, 768 / 32, 8), dim3(32, 8)>>>(attnbuf, kvbuf, oh, ol);

    // 6) out = o_pre @ W_proj^T + b_proj via HMMA split-fp16
    hmma_gemm<true><<<dim3(768 / 128, 32768 / 128), 256, GEMM_SMEM>>>(
        oh, ol, wph, wpl, out, bproj, 768, 768);
}

// round 4
// speedup vs baseline: 2.5772x; 1.1922x over previous
#include <cuda_runtime.h>
#include <cuda_fp16.h>
#include <cstdint>
#include <math.h>

// ============================================================================
// CrossAttention, compute_103-legal tensor cores (mma.sync fp16, 3-term split).
// Round 4: fused-chunk 3-term HMMA GEMM, 256x128 tile, 512 threads, BK=64,
// 2-stage cp.async; q projection moved onto the HMMA path.
// ============================================================================

// ---------------- scratch (device globals; allocation-free) ----------------
__device__ float  g_q[512 * 768];              // x @ Wq^T (fp32)
__device__ __half g_xh[393216],  g_xl[393216];
__device__ __half g_yh[25165824], g_yl[25165824];
__device__ __half g_wqkvh[1769472], g_wqkvl[1769472];
__device__ __half g_wph[589824], g_wpl[589824];
__device__ float  g_kv[32768L * 1536];         // y @ Wkv^T (fp32) [k | v]
__device__ float  g_attn[6144L * 4096];        // logits/softmax
__device__ __half g_oh[32768L * 768], g_ol[32768L * 768];

// ============================================================================
// low-level helpers (sm_80-level PTX; legal at compute_103)
// ============================================================================
__device__ __forceinline__ uint32_t smem_u32(const void* p) {
    uint32_t a;
    asm("{ .reg .u64 t; cvta.to.shared.u64 t, %1; cvt.u32.u64 %0, t; }" : "=r"(a) : "l"(p));
    return a;
}
__device__ __forceinline__ void cp_async16(uint32_t s, const void* g) {
    asm volatile("cp.async.cg.shared.global [%0], [%1], 16;\n" :: "r"(s), "l"(g));
}
__device__ __forceinline__ void cp_commit() { asm volatile("cp.async.commit_group;\n"); }
template <int N>
__device__ __forceinline__ void cp_wait() { asm volatile("cp.async.wait_group %0;\n" :: "n"(N)); }
__device__ __forceinline__ void ldsm_x4(uint32_t* r, uint32_t addr) {
    asm volatile("ldmatrix.sync.aligned.m8n8.x4.shared.b16 {%0,%1,%2,%3}, [%4];\n"
                 : "=r"(r[0]), "=r"(r[1]), "=r"(r[2]), "=r"(r[3]) : "r"(addr));
}
__device__ __forceinline__ void mma16816(float* c, const uint32_t* a, const uint32_t* b) {
    asm volatile("mma.sync.aligned.m16n8k16.row.col.f32.f16.f16.f32 "
                 "{%0,%1,%2,%3}, {%4,%5,%6,%7}, {%8,%9}, {%0,%1,%2,%3};\n"
                 : "+f"(c[0]), "+f"(c[1]), "+f"(c[2]), "+f"(c[3])
                 : "r"(a[0]), "r"(a[1]), "r"(a[2]), "r"(a[3]), "r"(b[0]), "r"(b[1]));
}

// ============================================================================
// Fused 3-term split HMMA GEMM: C[M,N] = A[M,K] @ B[N,K]^T (+bias)
// Block tile 256x128, BK=64, 512 threads (4x4 warps, 64x32 warp tile).
// Per chunk: load Ahi/Alo/Bhi/Blo; accumulate Ahi*Bhi + Ahi*Blo + Alo*Bhi.
// 2-stage cp.async pipeline; 192 KB dynamic smem.
// ============================================================================
static constexpr int STAGE_BYTES = 98304;   // 32K Ahi + 32K Alo + 16K Bhi + 16K Blo
static constexpr int GEMM_SMEM   = 2 * STAGE_BYTES;
static constexpr int OFF_ALO = 32768, OFF_BHI = 65536, OFF_BLO = 81920;

template <bool BIAS>
__global__ void __launch_bounds__(512, 1) hmma_gemm(
    const __half* __restrict__ Ahi, const __half* __restrict__ Alo,
    const __half* __restrict__ Bhi, const __half* __restrict__ Blo,
    float* __restrict__ C, const float* __restrict__ bias,
    int K, int ldC)
{
    extern __shared__ char smem[];
    const uint32_t sb = smem_u32(smem);
    const int tid  = threadIdx.x;
    const int wid  = tid >> 5;
    const int lane = tid & 31;
    const int m_warp = (wid & 3) * 64;
    const int n_warp = (wid >> 2) * 32;

    const size_t arow0 = (size_t)blockIdx.y * 256;
    const size_t brow0 = (size_t)blockIdx.x * 128;
    const int nChunks = K >> 6;

    const int lrow = tid >> 3;       // 0..63
    const int lch  = tid & 7;        // 16B chunk within 128B row

    auto issue_chunk = [&](int c) {
        const int k0 = c << 6;
        const uint32_t base = sb + (c & 1) * STAGE_BYTES;
        const size_t gk = (size_t)k0 + lch * 8;
        #pragma unroll
        for (int i = 0; i < 4; i++) {
            const int row = lrow + i * 64;
            const uint32_t so = row * 128 + ((lch ^ (row & 7)) << 4);
            cp_async16(base + so,            Ahi + (arow0 + row) * (size_t)K + gk);
            cp_async16(base + OFF_ALO + so,  Alo + (arow0 + row) * (size_t)K + gk);
        }
        #pragma unroll
        for (int i = 0; i < 2; i++) {
            const int row = lrow + i * 64;
            const uint32_t so = row * 128 + ((lch ^ (row & 7)) << 4);
            cp_async16(base + OFF_BHI + so,  Bhi + (brow0 + row) * (size_t)K + gk);
            cp_async16(base + OFF_BLO + so,  Blo + (brow0 + row) * (size_t)K + gk);
        }
    };

    float acc[4][4][4] = {};

    issue_chunk(0); cp_commit();

    for (int c = 0; c < nChunks; c++) {
        if (c + 1 < nChunks) { issue_chunk(c + 1); cp_commit(); cp_wait<1>(); }
        else                 { cp_wait<0>(); }
        __syncthreads();

        const uint32_t base = sb + (c & 1) * STAGE_BYTES;
        #pragma unroll
        for (int ks = 0; ks < 4; ks++) {
            // B fragments (hi and lo), n=32 per warp
            uint32_t bh[4][2], bl[4][2];
            {
                const int g = lane >> 3;
                const int nr = ((g >> 1) << 3) + (lane & 7);
                const int kk = ks * 16 + ((g & 1) << 3);
                #pragma unroll
                for (int nh = 0; nh < 2; nh++) {
                    const int r = n_warp + nh * 16 + nr;
                    const uint32_t so = r * 128 + ((((kk >> 3) ^ (r & 7))) << 4);
                    uint32_t r4[4];
                    ldsm_x4(r4, base + OFF_BHI + so);
                    bh[nh * 2][0] = r4[0]; bh[nh * 2][1] = r4[1];
                    bh[nh * 2 + 1][0] = r4[2]; bh[nh * 2 + 1][1] = r4[3];
                    ldsm_x4(r4, base + OFF_BLO + so);
                    bl[nh * 2][0] = r4[0]; bl[nh * 2][1] = r4[1];
                    bl[nh * 2 + 1][0] = r4[2]; bl[nh * 2 + 1][1] = r4[3];
                }
            }
            // A fragments: hi first, two MMA combos, then reuse regs for lo
            uint32_t afr[4][4];
            const int ar = m_warp + (lane & 15);
            const int akk = ks * 16 + (lane >> 4) * 8;
            const uint32_t aso = ((((akk >> 3))) << 4);
            #pragma unroll
            for (int mi = 0; mi < 4; mi++) {
                const int r = ar + mi * 16;
                ldsm_x4(afr[mi], base + r * 128 + (((akk >> 3) ^ (r & 7)) << 4));
            }
            #pragma unroll
            for (int mi = 0; mi < 4; mi++)
                #pragma unroll
                for (int ni = 0; ni < 4; ni++)
                    mma16816(acc[mi][ni], afr[mi], bh[ni]);
            #pragma unroll
            for (int mi = 0; mi < 4; mi++)
                #pragma unroll
                for (int ni = 0; ni < 4; ni++)
                    mma16816(acc[mi][ni], afr[mi], bl[ni]);
            #pragma unroll
            for (int mi = 0; mi < 4; mi++) {
                const int r = ar + mi * 16;
                ldsm_x4(afr[mi], base + OFF_ALO + r * 128 + (((akk >> 3) ^ (r & 7)) << 4));
            }
            #pragma unroll
            for (int mi = 0; mi < 4; mi++)
                #pragma unroll
                for (int ni = 0; ni < 4; ni++)
                    mma16816(acc[mi][ni], afr[mi], bh[ni]);
            (void)aso;
        }
        __syncthreads();   // all warps done with this stage before it is overwritten
    }

    // epilogue
    const int mg0 = (int)arow0 + m_warp + (lane >> 2);
    const int ng0 = (int)brow0 + n_warp + (lane & 3) * 2;
    #pragma unroll
    for (int mi = 0; mi < 4; mi++) {
        #pragma unroll
        for (int ni = 0; ni < 4; ni++) {
            const int m = mg0 + mi * 16;
            const int n = ng0 + ni * 8;
            float2 v0 = { acc[mi][ni][0], acc[mi][ni][1] };
            float2 v1 = { acc[mi][ni][2], acc[mi][ni][3] };
            if (BIAS) {
                const float2 bv = *(const float2*)&bias[n];
                v0.x += bv.x; v0.y += bv.y; v1.x += bv.x; v1.y += bv.y;
            }
            *(float2*)&C[(size_t)m * ldC + n] = v0;
            *(float2*)&C[(size_t)(m + 8) * ldC + n] = v1;
        }
    }
}

// ============================================================================
// fp32 -> (hi, lo) fp16 split conversion
// ============================================================================
__device__ __forceinline__ void split_h(float x, __half& h, __half& l) {
    h = __float2half_rn(x);
    l = __float2half_rn(x - __half2float(h));
}

__global__ void __launch_bounds__(256) conv_split4(const float* __restrict__ in,
                                                   __half* __restrict__ hi,
                                                   __half* __restrict__ lo, int n4)
{
    const int i = blockIdx.x * blockDim.x + threadIdx.x;
    if (i >= n4) return;
    const float4 v = *(const float4*)&in[i * 4];
    __half h[4], l[4];
    split_h(v.x, h[0], l[0]); split_h(v.y, h[1], l[1]);
    split_h(v.z, h[2], l[2]); split_h(v.w, h[3], l[3]);
    *(uint2*)&hi[i * 4] = *(uint2*)h;
    *(uint2*)&lo[i * 4] = *(uint2*)l;
}

// ============================================================================
// attention logits (fp32): attn[b*768+h*64+i][j] = scale * q_bh[i,:]·k_bh[j,:]
// ============================================================================
__global__ void __launch_bounds__(256) attn_logits(
    const float* __restrict__ q, const float* __restrict__ kv, float* __restrict__ attn)
{
    const int bh = blockIdx.y;
    const int b = bh / 12, h = bh % 12;
    const int j0 = blockIdx.x * 128;
    __shared__ float Qs[64][65];
    __shared__ float Ks[128][65];
    const int tid = threadIdx.x;
    for (int t = tid; t < 64 * 16; t += 256) {
        const int i = t >> 4; const int d4 = (t & 15) << 2;
        float4 v = *(const float4*)&q[(size_t)(b * 64 + i) * 768 + h * 64 + d4];
        Qs[i][d4] = v.x; Qs[i][d4 + 1] = v.y; Qs[i][d4 + 2] = v.z; Qs[i][d4 + 3] = v.w;
    }
    for (int t = tid; t < 128 * 16; t += 256) {
        const int j = t >> 4; const int d4 = (t & 15) << 2;
        float4 v = *(const float4*)&kv[(size_t)(b * 4096 + j0 + j) * 1536 + h * 64 + d4];
        Ks[j][d4] = v.x; Ks[j][d4 + 1] = v.y; Ks[j][d4 + 2] = v.z; Ks[j][d4 + 3] = v.w;
    }
    __syncthreads();
    const int trow = (tid >> 4) * 4;
    const int tcol = tid & 15;
    float acc[4][8] = {};
    #pragma unroll 4
    for (int d = 0; d < 64; d++) {
        float qr[4], kr[8];
        #pragma unroll
        for (int i = 0; i < 4; i++) qr[i] = Qs[trow + i][d];
        #pragma unroll
        for (int j = 0; j < 8; j++) kr[j] = Ks[tcol + 16 * j][d];
        #pragma unroll
        for (int i = 0; i < 4; i++)
            #pragma unroll
            for (int j = 0; j < 8; j++) acc[i][j] = fmaf(qr[i], kr[j], acc[i][j]);
    }
    #pragma unroll
    for (int i = 0; i < 4; i++) {
        float* row = attn + (size_t)(b * 768 + h * 64 + trow + i) * 4096 + j0;
        #pragma unroll
        for (int j = 0; j < 8; j++) row[tcol + 16 * j] = acc[i][j] * 0.125f;
    }
}

// ============================================================================
// row softmax over 4096
// ============================================================================
__global__ void __launch_bounds__(256) softmax4096(float* __restrict__ a)
{
    float* p = a + (size_t)blockIdx.x * 4096;
    const int tid = threadIdx.x;
    float4 v[4];
    #pragma unroll
    for (int t = 0; t < 4; t++) v[t] = *(const float4*)&p[tid * 4 + t * 1024];
    float m = -1e30f;
    #pragma unroll
    for (int t = 0; t < 4; t++)
        m = fmaxf(m, fmaxf(fmaxf(v[t].x, v[t].y), fmaxf(v[t].z, v[t].w)));
    __shared__ float sh[8];
    #pragma unroll
    for (int o = 16; o; o >>= 1) m = fmaxf(m, __shfl_xor_sync(0xffffffffu, m, o));
    if ((tid & 31) == 0) sh[tid >> 5] = m;
    __syncthreads();
    m = fmaxf(fmaxf(fmaxf(sh[0], sh[1]), fmaxf(sh[2], sh[3])),
              fmaxf(fmaxf(sh[4], sh[5]), fmaxf(sh[6], sh[7])));
    float s = 0.f;
    #pragma unroll
    for (int t = 0; t < 4; t++) {
        v[t].x = __expf(v[t].x - m); v[t].y = __expf(v[t].y - m);
        v[t].z = __expf(v[t].z - m); v[t].w = __expf(v[t].w - m);
        s += v[t].x + v[t].y + v[t].z + v[t].w;
    }
    __syncthreads();
    #pragma unroll
    for (int o = 16; o; o >>= 1) s += __shfl_xor_sync(0xffffffffu, s, o);
    if ((tid & 31) == 0) sh[tid >> 5] = s;
    __syncthreads();
    s = sh[0] + sh[1] + sh[2] + sh[3] + sh[4] + sh[5] + sh[6] + sh[7];
    const float inv = 1.0f / s;
    #pragma unroll
    for (int t = 0; t < 4; t++) {
        v[t].x *= inv; v[t].y *= inv; v[t].z *= inv; v[t].w *= inv;
        *(float4*)&p[tid * 4 + t * 1024] = v[t];
    }
}

// ============================================================================
// o_pre = attn^T * v, emitted as (hi, lo) fp16 split
// ============================================================================
__global__ void __launch_bounds__(256) trans_mul_split(
    const float* __restrict__ attn, const float* __restrict__ kv,
    __half* __restrict__ ohi, __half* __restrict__ olo)
{
    __shared__ float tile[32][33];
    const int b = blockIdx.z;
    const int n0 = blockIdx.x * 32;
    const int c0 = blockIdx.y * 32;
    const int tx = threadIdx.x, ty = threadIdx.y;
    #pragma unroll
    for (int r = ty; r < 32; r += 8)
        tile[r][tx] = attn[(size_t)(b * 768 + c0 + r) * 4096 + n0 + tx];
    __syncthreads();
    #pragma unroll
    for (int r = ty; r < 32; r += 8) {
        const int n = n0 + r, c = c0 + tx;
        const float vv = kv[(size_t)(b * 4096 + n) * 1536 + 768 + c];
        const float o = tile[tx][r] * vv;
        __half h, l; split_h(o, h, l);
        const size_t idx = (size_t)(b * 4096 + n) * 768 + c;
        ohi[idx] = h; olo[idx] = l;
    }
}

// ============================================================================
// launch
// ============================================================================
extern "C" void kernel_launch(void* const* d_in, const int* in_sizes, int n_in,
                              void* d_out, int out_size)
{
    const float *x = nullptr, *y = nullptr, *Wqkv = nullptr, *Wproj = nullptr, *bproj = nullptr;
    for (int i = 0; i < n_in; i++) {
        switch (in_sizes[i]) {
            case 393216:   x     = (const float*)d_in[i]; break;
            case 25165824: y     = (const float*)d_in[i]; break;
            case 1769472:  Wqkv  = (const float*)d_in[i]; break;
            case 589824:   Wproj = (const float*)d_in[i]; break;
            case 768:      bproj = (const float*)d_in[i]; break;
        }
    }
    float* out = (float*)d_out;

    float *qbuf, *kvbuf, *attnbuf;
    __half *xh, *xl, *yh, *yl, *wqkvh, *wqkvl, *wph, *wpl, *oh, *ol;
    cudaGetSymbolAddress((void**)&qbuf,    g_q);
    cudaGetSymbolAddress((void**)&kvbuf,   g_kv);
    cudaGetSymbolAddress((void**)&attnbuf, g_attn);
    cudaGetSymbolAddress((void**)&xh,    g_xh);
    cudaGetSymbolAddress((void**)&xl,    g_xl);
    cudaGetSymbolAddress((void**)&yh,    g_yh);
    cudaGetSymbolAddress((void**)&yl,    g_yl);
    cudaGetSymbolAddress((void**)&wqkvh, g_wqkvh);
    cudaGetSymbolAddress((void**)&wqkvl, g_wqkvl);
    cudaGetSymbolAddress((void**)&wph,   g_wph);
    cudaGetSymbolAddress((void**)&wpl,   g_wpl);
    cudaGetSymbolAddress((void**)&oh,    g_oh);
    cudaGetSymbolAddress((void**)&ol,    g_ol);

    cudaFuncSetAttribute(hmma_gemm<false>, cudaFuncAttributeMaxDynamicSharedMemorySize, GEMM_SMEM);
    cudaFuncSetAttribute(hmma_gemm<true>,  cudaFuncAttributeMaxDynamicSharedMemorySize, GEMM_SMEM);

    // 0) fp32 -> fp16 hi/lo splits
    conv_split4<<<393216 / 4 / 256, 256>>>(x, xh, xl, 393216 / 4);
    conv_split4<<<1769472 / 4 / 256, 256>>>(Wqkv, wqkvh, wqkvl, 1769472 / 4);
    conv_split4<<<589824 / 4 / 256, 256>>>(Wproj, wph, wpl, 589824 / 4);
    conv_split4<<<25165824 / 4 / 256, 256>>>(y, yh, yl, 25165824 / 4);

    // 1) q = x @ Wq^T : [512,768] x [768,768] (Wq = rows 0..767 of W_qkv)
    hmma_gemm<false><<<dim3(768 / 128, 512 / 256), 512, GEMM_SMEM>>>(
        xh, xl, wqkvh, wqkvl, qbuf, nullptr, 768, 768);

    // 2) kv = y @ Wkv^T : [32768,768] x [1536,768] (Wkv = rows 768.. of W_qkv)
    hmma_gemm<false><<<dim3(1536 / 128, 32768 / 256), 512, GEMM_SMEM>>>(
        yh, yl, wqkvh + 768 * 768, wqkvl + 768 * 768, kvbuf, nullptr, 768, 1536);

    // 3) logits
    attn_logits<<<dim3(4096 / 128, 8 * 12), 256>>>(qbuf, kvbuf, attnbuf);

    // 4) softmax
    softmax4096<<<6144, 256>>>(attnbuf);

    // 5) attn_t * v -> fp16 hi/lo
    trans_mul_split<<<dim3(4096 / 32, 768 / 32, 8), dim3(32, 8)>>>(attnbuf, kvbuf, oh, ol);

    // 6) out = o_pre @ W_proj^T + b_proj
    hmma_gemm<true><<<dim3(768 / 128, 32768 / 256), 512, GEMM_SMEM>>>(
        oh, ol, wph, wpl, out, bproj, 768, 768);
}

// round 5
// speedup vs baseline: 3.3281x; 1.2914x over previous
#include <cuda_runtime.h>
#include <cuda_fp16.h>
#include <cstdint>
#include <math.h>

// ============================================================================
// CrossAttention, compute_103-legal tensor cores (mma.sync fp16).
// Round 5: 2-term split GEMM (Ahi*Bhi + Alo*Bhi; weights pure fp16),
// o_pre scaled by 2^13 before fp16 split (fixes subnormal lo), unscaled in
// the proj epilogue. 256x128 tile, 512 threads, BK=64, 2-stage cp.async.
// ============================================================================

// ---------------- scratch (device globals; allocation-free) ----------------
__device__ float  g_q[512 * 768];               // x @ Wq^T (fp32)
__device__ __half g_xh[393216],  g_xl[393216];
__device__ __half g_yh[25165824], g_yl[25165824];
__device__ __half g_wqkvh[1769472];             // weights: hi only
__device__ __half g_wph[589824];
__device__ float  g_kv[32768L * 1536];          // y @ Wkv^T (fp32) [k | v]
__device__ float  g_attn[6144L * 4096];         // logits/softmax
__device__ __half g_oh[32768L * 768], g_ol[32768L * 768];  // o * 2^13 split

// ============================================================================
// low-level helpers (sm_80-level PTX; legal at compute_103)
// ============================================================================
__device__ __forceinline__ uint32_t smem_u32(const void* p) {
    uint32_t a;
    asm("{ .reg .u64 t; cvta.to.shared.u64 t, %1; cvt.u32.u64 %0, t; }" : "=r"(a) : "l"(p));
    return a;
}
__device__ __forceinline__ void cp_async16(uint32_t s, const void* g) {
    asm volatile("cp.async.cg.shared.global [%0], [%1], 16;\n" :: "r"(s), "l"(g));
}
__device__ __forceinline__ void cp_commit() { asm volatile("cp.async.commit_group;\n"); }
template <int N>
__device__ __forceinline__ void cp_wait() { asm volatile("cp.async.wait_group %0;\n" :: "n"(N)); }
__device__ __forceinline__ void ldsm_x4(uint32_t* r, uint32_t addr) {
    asm volatile("ldmatrix.sync.aligned.m8n8.x4.shared.b16 {%0,%1,%2,%3}, [%4];\n"
                 : "=r"(r[0]), "=r"(r[1]), "=r"(r[2]), "=r"(r[3]) : "r"(addr));
}
__device__ __forceinline__ void mma16816(float* c, const uint32_t* a, const uint32_t* b) {
    asm volatile("mma.sync.aligned.m16n8k16.row.col.f32.f16.f16.f32 "
                 "{%0,%1,%2,%3}, {%4,%5,%6,%7}, {%8,%9}, {%0,%1,%2,%3};\n"
                 : "+f"(c[0]), "+f"(c[1]), "+f"(c[2]), "+f"(c[3])
                 : "r"(a[0]), "r"(a[1]), "r"(a[2]), "r"(a[3]), "r"(b[0]), "r"(b[1]));
}

// ============================================================================
// 2-term split HMMA GEMM: C[M,N] = (Ahi + Alo)[M,K] @ Bhi[N,K]^T * scale (+bias)
// Block tile 256x128, BK=64, 512 threads (4x4 warps, 64x32 warp tile).
// 2-stage cp.async pipeline; 160 KB dynamic smem.
// ============================================================================
static constexpr int OFF_ALO = 32768, OFF_BHI = 65536;
static constexpr int STAGE_BYTES = 81920;   // 32K Ahi + 32K Alo + 16K Bhi
static constexpr int GEMM_SMEM   = 2 * STAGE_BYTES;   // 160 KB

template <bool BIAS>
__global__ void __launch_bounds__(512, 1) hmma_gemm(
    const __half* __restrict__ Ahi, const __half* __restrict__ Alo,
    const __half* __restrict__ Bhi,
    float* __restrict__ C, const float* __restrict__ bias,
    int K, int ldC, float out_scale)
{
    extern __shared__ char smem[];
    const uint32_t sb = smem_u32(smem);
    const int tid  = threadIdx.x;
    const int wid  = tid >> 5;
    const int lane = tid & 31;
    const int m_warp = (wid & 3) * 64;
    const int n_warp = (wid >> 2) * 32;

    const size_t arow0 = (size_t)blockIdx.y * 256;
    const size_t brow0 = (size_t)blockIdx.x * 128;
    const int nChunks = K >> 6;

    const int lrow = tid >> 3;       // 0..63
    const int lch  = tid & 7;        // 16B chunk within 128B row

    auto issue_chunk = [&](int c) {
        const int k0 = c << 6;
        const uint32_t base = sb + (c & 1) * STAGE_BYTES;
        const size_t gk = (size_t)k0 + lch * 8;
        #pragma unroll
        for (int i = 0; i < 4; i++) {
            const int row = lrow + i * 64;
            const uint32_t so = row * 128 + ((lch ^ (row & 7)) << 4);
            cp_async16(base + so,           Ahi + (arow0 + row) * (size_t)K + gk);
            cp_async16(base + OFF_ALO + so, Alo + (arow0 + row) * (size_t)K + gk);
        }
        #pragma unroll
        for (int i = 0; i < 2; i++) {
            const int row = lrow + i * 64;
            const uint32_t so = row * 128 + ((lch ^ (row & 7)) << 4);
            cp_async16(base + OFF_BHI + so, Bhi + (brow0 + row) * (size_t)K + gk);
        }
    };

    float acc[4][4][4] = {};

    issue_chunk(0); cp_commit();

    for (int c = 0; c < nChunks; c++) {
        if (c + 1 < nChunks) { issue_chunk(c + 1); cp_commit(); cp_wait<1>(); }
        else                 { cp_wait<0>(); }
        __syncthreads();

        const uint32_t base = sb + (c & 1) * STAGE_BYTES;
        #pragma unroll
        for (int ks = 0; ks < 4; ks++) {
            // B fragments (hi only), n=32 per warp
            uint32_t bh[4][2];
            {
                const int g = lane >> 3;
                const int nr = ((g >> 1) << 3) + (lane & 7);
                const int kk = ks * 16 + ((g & 1) << 3);
                #pragma unroll
                for (int nh = 0; nh < 2; nh++) {
                    const int r = n_warp + nh * 16 + nr;
                    const uint32_t so = r * 128 + ((((kk >> 3) ^ (r & 7))) << 4);
                    uint32_t r4[4];
                    ldsm_x4(r4, base + OFF_BHI + so);
                    bh[nh * 2][0] = r4[0]; bh[nh * 2][1] = r4[1];
                    bh[nh * 2 + 1][0] = r4[2]; bh[nh * 2 + 1][1] = r4[3];
                }
            }
            // A fragments: hi, MMAs, then reuse regs for lo
            uint32_t afr[4][4];
            const int ar = m_warp + (lane & 15);
            const int akk = ks * 16 + (lane >> 4) * 8;
            #pragma unroll
            for (int mi = 0; mi < 4; mi++) {
                const int r = ar + mi * 16;
                ldsm_x4(afr[mi], base + r * 128 + (((akk >> 3) ^ (r & 7)) << 4));
            }
            #pragma unroll
            for (int mi = 0; mi < 4; mi++)
                #pragma unroll
                for (int ni = 0; ni < 4; ni++)
                    mma16816(acc[mi][ni], afr[mi], bh[ni]);
            #pragma unroll
            for (int mi = 0; mi < 4; mi++) {
                const int r = ar + mi * 16;
                ldsm_x4(afr[mi], base + OFF_ALO + r * 128 + (((akk >> 3) ^ (r & 7)) << 4));
            }
            #pragma unroll
            for (int mi = 0; mi < 4; mi++)
                #pragma unroll
                for (int ni = 0; ni < 4; ni++)
                    mma16816(acc[mi][ni], afr[mi], bh[ni]);
        }
        __syncthreads();
    }

    // epilogue
    const int mg0 = (int)arow0 + m_warp + (lane >> 2);
    const int ng0 = (int)brow0 + n_warp + (lane & 3) * 2;
    #pragma unroll
    for (int mi = 0; mi < 4; mi++) {
        #pragma unroll
        for (int ni = 0; ni < 4; ni++) {
            const int m = mg0 + mi * 16;
            const int n = ng0 + ni * 8;
            float2 v0 = { acc[mi][ni][0] * out_scale, acc[mi][ni][1] * out_scale };
            float2 v1 = { acc[mi][ni][2] * out_scale, acc[mi][ni][3] * out_scale };
            if (BIAS) {
                const float2 bv = *(const float2*)&bias[n];
                v0.x += bv.x; v0.y += bv.y; v1.x += bv.x; v1.y += bv.y;
            }
            *(float2*)&C[(size_t)m * ldC + n] = v0;
            *(float2*)&C[(size_t)(m + 8) * ldC + n] = v1;
        }
    }
}

// ============================================================================
// conversions
// ============================================================================
__device__ __forceinline__ void split_h(float x, __half& h, __half& l) {
    h = __float2half_rn(x);
    l = __float2half_rn(x - __half2float(h));
}

__global__ void __launch_bounds__(256) conv_split4(const float* __restrict__ in,
                                                   __half* __restrict__ hi,
                                                   __half* __restrict__ lo, int n4)
{
    const int i = blockIdx.x * blockDim.x + threadIdx.x;
    if (i >= n4) return;
    const float4 v = *(const float4*)&in[i * 4];
    __half h[4], l[4];
    split_h(v.x, h[0], l[0]); split_h(v.y, h[1], l[1]);
    split_h(v.z, h[2], l[2]); split_h(v.w, h[3], l[3]);
    *(uint2*)&hi[i * 4] = *(uint2*)h;
    *(uint2*)&lo[i * 4] = *(uint2*)l;
}

__global__ void __launch_bounds__(256) conv_hi4(const float* __restrict__ in,
                                                __half* __restrict__ hi, int n4)
{
    const int i = blockIdx.x * blockDim.x + threadIdx.x;
    if (i >= n4) return;
    const float4 v = *(const float4*)&in[i * 4];
    __half h[4] = { __float2half_rn(v.x), __float2half_rn(v.y),
                    __float2half_rn(v.z), __float2half_rn(v.w) };
    *(uint2*)&hi[i * 4] = *(uint2*)h;
}

// ============================================================================
// attention logits (fp32): attn[b*768+h*64+i][j] = scale * q_bh[i,:]·k_bh[j,:]
// ============================================================================
__global__ void __launch_bounds__(256) attn_logits(
    const float* __restrict__ q, const float* __restrict__ kv, float* __restrict__ attn)
{
    const int bh = blockIdx.y;
    const int b = bh / 12, h = bh % 12;
    const int j0 = blockIdx.x * 128;
    __shared__ float Qs[64][65];
    __shared__ float Ks[128][65];
    const int tid = threadIdx.x;
    for (int t = tid; t < 64 * 16; t += 256) {
        const int i = t >> 4; const int d4 = (t & 15) << 2;
        float4 v = *(const float4*)&q[(size_t)(b * 64 + i) * 768 + h * 64 + d4];
        Qs[i][d4] = v.x; Qs[i][d4 + 1] = v.y; Qs[i][d4 + 2] = v.z; Qs[i][d4 + 3] = v.w;
    }
    for (int t = tid; t < 128 * 16; t += 256) {
        const int j = t >> 4; const int d4 = (t & 15) << 2;
        float4 v = *(const float4*)&kv[(size_t)(b * 4096 + j0 + j) * 1536 + h * 64 + d4];
        Ks[j][d4] = v.x; Ks[j][d4 + 1] = v.y; Ks[j][d4 + 2] = v.z; Ks[j][d4 + 3] = v.w;
    }
    __syncthreads();
    const int trow = (tid >> 4) * 4;
    const int tcol = tid & 15;
    float acc[4][8] = {};
    #pragma unroll 4
    for (int d = 0; d < 64; d++) {
        float qr[4], kr[8];
        #pragma unroll
        for (int i = 0; i < 4; i++) qr[i] = Qs[trow + i][d];
        #pragma unroll
        for (int j = 0; j < 8; j++) kr[j] = Ks[tcol + 16 * j][d];
        #pragma unroll
        for (int i = 0; i < 4; i++)
            #pragma unroll
            for (int j = 0; j < 8; j++) acc[i][j] = fmaf(qr[i], kr[j], acc[i][j]);
    }
    #pragma unroll
    for (int i = 0; i < 4; i++) {
        float* row = attn + (size_t)(b * 768 + h * 64 + trow + i) * 4096 + j0;
        #pragma unroll
        for (int j = 0; j < 8; j++) row[tcol + 16 * j] = acc[i][j] * 0.125f;
    }
}

// ============================================================================
// row softmax over 4096
// ============================================================================
__global__ void __launch_bounds__(256) softmax4096(float* __restrict__ a)
{
    float* p = a + (size_t)blockIdx.x * 4096;
    const int tid = threadIdx.x;
    float4 v[4];
    #pragma unroll
    for (int t = 0; t < 4; t++) v[t] = *(const float4*)&p[tid * 4 + t * 1024];
    float m = -1e30f;
    #pragma unroll
    for (int t = 0; t < 4; t++)
        m = fmaxf(m, fmaxf(fmaxf(v[t].x, v[t].y), fmaxf(v[t].z, v[t].w)));
    __shared__ float sh[8];
    #pragma unroll
    for (int o = 16; o; o >>= 1) m = fmaxf(m, __shfl_xor_sync(0xffffffffu, m, o));
    if ((tid & 31) == 0) sh[tid >> 5] = m;
    __syncthreads();
    m = fmaxf(fmaxf(fmaxf(sh[0], sh[1]), fmaxf(sh[2], sh[3])),
              fmaxf(fmaxf(sh[4], sh[5]), fmaxf(sh[6], sh[7])));
    float s = 0.f;
    #pragma unroll
    for (int t = 0; t < 4; t++) {
        v[t].x = __expf(v[t].x - m); v[t].y = __expf(v[t].y - m);
        v[t].z = __expf(v[t].z - m); v[t].w = __expf(v[t].w - m);
        s += v[t].x + v[t].y + v[t].z + v[t].w;
    }
    __syncthreads();
    #pragma unroll
    for (int o = 16; o; o >>= 1) s += __shfl_xor_sync(0xffffffffu, s, o);
    if ((tid & 31) == 0) sh[tid >> 5] = s;
    __syncthreads();
    s = sh[0] + sh[1] + sh[2] + sh[3] + sh[4] + sh[5] + sh[6] + sh[7];
    const float inv = 1.0f / s;
    #pragma unroll
    for (int t = 0; t < 4; t++) {
        v[t].x *= inv; v[t].y *= inv; v[t].z *= inv; v[t].w *= inv;
        *(float4*)&p[tid * 4 + t * 1024] = v[t];
    }
}

// ============================================================================
// o_pre = (attn^T * v) * 2^13, emitted as (hi, lo) fp16 split.
// The 2^13 pre-scale keeps the lo component out of fp16 subnormal range;
// the proj GEMM epilogue multiplies by 2^-13.
// ============================================================================
__global__ void __launch_bounds__(256) trans_mul_split(
    const float* __restrict__ attn, const float* __restrict__ kv,
    __half* __restrict__ ohi, __half* __restrict__ olo)
{
    __shared__ float tile[32][33];
    const int b = blockIdx.z;
    const int n0 = blockIdx.x * 32;
    const int c0 = blockIdx.y * 32;
    const int tx = threadIdx.x, ty = threadIdx.y;
    #pragma unroll
    for (int r = ty; r < 32; r += 8)
        tile[r][tx] = attn[(size_t)(b * 768 + c0 + r) * 4096 + n0 + tx];
    __syncthreads();
    #pragma unroll
    for (int r = ty; r < 32; r += 8) {
        const int n = n0 + r, c = c0 + tx;
        const float vv = kv[(size_t)(b * 4096 + n) * 1536 + 768 + c];
        const float o = tile[tx][r] * vv * 8192.0f;
        __half h, l; split_h(o, h, l);
        const size_t idx = (size_t)(b * 4096 + n) * 768 + c;
        ohi[idx] = h; olo[idx] = l;
    }
}

// ============================================================================
// launch
// ============================================================================
extern "C" void kernel_launch(void* const* d_in, const int* in_sizes, int n_in,
                              void* d_out, int out_size)
{
    const float *x = nullptr, *y = nullptr, *Wqkv = nullptr, *Wproj = nullptr, *bproj = nullptr;
    for (int i = 0; i < n_in; i++) {
        switch (in_sizes[i]) {
            case 393216:   x     = (const float*)d_in[i]; break;
            case 25165824: y     = (const float*)d_in[i]; break;
            case 1769472:  Wqkv  = (const float*)d_in[i]; break;
            case 589824:   Wproj = (const float*)d_in[i]; break;
            case 768:      bproj = (const float*)d_in[i]; break;
        }
    }
    float* out = (float*)d_out;

    float *qbuf, *kvbuf, *attnbuf;
    __half *xh, *xl, *yh, *yl, *wqkvh, *wph, *oh, *ol;
    cudaGetSymbolAddress((void**)&qbuf,    g_q);
    cudaGetSymbolAddress((void**)&kvbuf,   g_kv);
    cudaGetSymbolAddress((void**)&attnbuf, g_attn);
    cudaGetSymbolAddress((void**)&xh,    g_xh);
    cudaGetSymbolAddress((void**)&xl,    g_xl);
    cudaGetSymbolAddress((void**)&yh,    g_yh);
    cudaGetSymbolAddress((void**)&yl,    g_yl);
    cudaGetSymbolAddress((void**)&wqkvh, g_wqkvh);
    cudaGetSymbolAddress((void**)&wph,   g_wph);
    cudaGetSymbolAddress((void**)&oh,    g_oh);
    cudaGetSymbolAddress((void**)&ol,    g_ol);

    cudaFuncSetAttribute(hmma_gemm<false>, cudaFuncAttributeMaxDynamicSharedMemorySize, GEMM_SMEM);
    cudaFuncSetAttribute(hmma_gemm<true>,  cudaFuncAttributeMaxDynamicSharedMemorySize, GEMM_SMEM);

    // 0) conversions
    conv_split4<<<393216 / 4 / 256, 256>>>(x, xh, xl, 393216 / 4);
    conv_hi4<<<1769472 / 4 / 256, 256>>>(Wqkv, wqkvh, 1769472 / 4);
    conv_hi4<<<589824 / 4 / 256, 256>>>(Wproj, wph, 589824 / 4);
    conv_split4<<<25165824 / 4 / 256, 256>>>(y, yh, yl, 25165824 / 4);

    // 1) q = x @ Wq^T : [512,768] x [768,768]
    hmma_gemm<false><<<dim3(768 / 128, 512 / 256), 512, GEMM_SMEM>>>(
        xh, xl, wqkvh, qbuf, nullptr, 768, 768, 1.0f);

    // 2) kv = y @ Wkv^T : [32768,768] x [1536,768]
    hmma_gemm<false><<<dim3(1536 / 128, 32768 / 256), 512, GEMM_SMEM>>>(
        yh, yl, wqkvh + 768 * 768, kvbuf, nullptr, 768, 1536, 1.0f);

    // 3) logits
    attn_logits<<<dim3(4096 / 128, 8 * 12), 256>>>(qbuf, kvbuf, attnbuf);

    // 4) softmax
    softmax4096<<<6144, 256>>>(attnbuf);

    // 5) attn_t * v (scaled 2^13) -> fp16 hi/lo
    trans_mul_split<<<dim3(4096 / 32, 768 / 32, 8), dim3(32, 8)>>>(attnbuf, kvbuf, oh, ol);

    // 6) out = o_pre @ W_proj^T * 2^-13 + b_proj
    hmma_gemm<true><<<dim3(768 / 128, 32768 / 256), 512, GEMM_SMEM>>>(
        oh, ol, wph, out, bproj, 768, 768, 1.0f / 8192.0f);
}